// round 1
// baseline (speedup 1.0000x reference)
#include <cuda_runtime.h>

#define LBL 32
#define WPB 8   // warps per block in the level kernel

// Static device scratch (allocation-free per harness rules).
__device__ __align__(16) float g_expT[LBL * LBL];
__device__ __align__(16) float g_bufA[65536 * LBL];
__device__ __align__(16) float g_bufB[65536 * LBL];

// ---------------------------------------------------------------------------
// Precompute expT = exp(trans)  (runs once per kernel_launch; 1024 elements)
// ---------------------------------------------------------------------------
__global__ void expT_kernel(const float* __restrict__ trans) {
    int i = blockIdx.x * blockDim.x + threadIdx.x;
    if (i < LBL * LBL) g_expT[i] = __expf(trans[i]);
}

// ---------------------------------------------------------------------------
// Per-node compute: out[l] = em[l] + maxL + maxR + log(dot(expT[l,:], eL)) +
//                   log(dot(expT[l,:], eR))
// Warp-collective: lane doubles as child index m (load/exp) and label l (dot).
// ---------------------------------------------------------------------------
__device__ __forceinline__ float node_compute(
    const float* __restrict__ child,   // 2*level rows of 32
    const float* __restrict__ em,      // level rows of 32
    int node, int lane,
    float* __restrict__ s_el,          // 32 floats, 16B aligned, per-warp
    float* __restrict__ s_er,
    const float rT[LBL])               // expT row `lane`, in registers
{
    float lv = child[(2 * node) * LBL + lane];
    float rv = child[(2 * node) * LBL + LBL + lane];

    // warp max-reduce both children
    float ml = lv, mr = rv;
    #pragma unroll
    for (int o = 16; o; o >>= 1) {
        ml = fmaxf(ml, __shfl_xor_sync(0xffffffffu, ml, o));
        mr = fmaxf(mr, __shfl_xor_sync(0xffffffffu, mr, o));
    }

    s_el[lane] = __expf(lv - ml);
    s_er[lane] = __expf(rv - mr);
    __syncwarp();

    // dot(expT[lane,:], e{l,r}) — broadcast LDS.128 reads, 2 accumulators each
    const float4* pel = (const float4*)s_el;
    const float4* per = (const float4*)s_er;
    float aL0 = 0.f, aL1 = 0.f, aR0 = 0.f, aR1 = 0.f;
    #pragma unroll
    for (int j = 0; j < 8; j += 2) {
        float4 a0 = pel[j], b0 = per[j];
        float4 a1 = pel[j + 1], b1 = per[j + 1];
        aL0 = fmaf(rT[4 * j + 0], a0.x, aL0);
        aL0 = fmaf(rT[4 * j + 1], a0.y, aL0);
        aL0 = fmaf(rT[4 * j + 2], a0.z, aL0);
        aL0 = fmaf(rT[4 * j + 3], a0.w, aL0);
        aL1 = fmaf(rT[4 * j + 4], a1.x, aL1);
        aL1 = fmaf(rT[4 * j + 5], a1.y, aL1);
        aL1 = fmaf(rT[4 * j + 6], a1.z, aL1);
        aL1 = fmaf(rT[4 * j + 7], a1.w, aL1);
        aR0 = fmaf(rT[4 * j + 0], b0.x, aR0);
        aR0 = fmaf(rT[4 * j + 1], b0.y, aR0);
        aR0 = fmaf(rT[4 * j + 2], b0.z, aR0);
        aR0 = fmaf(rT[4 * j + 3], b0.w, aR0);
        aR1 = fmaf(rT[4 * j + 4], b1.x, aR1);
        aR1 = fmaf(rT[4 * j + 5], b1.y, aR1);
        aR1 = fmaf(rT[4 * j + 6], b1.z, aR1);
        aR1 = fmaf(rT[4 * j + 7], b1.w, aR1);
    }
    float res = em[node * LBL + lane] + ml + mr +
                __logf(aL0 + aL1) + __logf(aR0 + aR1);
    __syncwarp();   // protect shared staging before next iteration's writes
    return res;
}

__device__ __forceinline__ void load_rowT(float rT[LBL], int lane) {
    #pragma unroll
    for (int j = 0; j < 8; j++) {
        float4 v = ((const float4*)g_expT)[lane * 8 + j];
        rT[4 * j + 0] = v.x; rT[4 * j + 1] = v.y;
        rT[4 * j + 2] = v.z; rT[4 * j + 3] = v.w;
    }
}

// ---------------------------------------------------------------------------
// One tree level: warp-per-node, grid-stride over nodes.
// ---------------------------------------------------------------------------
__global__ void __launch_bounds__(WPB * 32)
level_kernel(const float* __restrict__ child,
             const float* __restrict__ em,
             float* __restrict__ out,
             int level)
{
    __shared__ __align__(16) float s_e[WPB][2][LBL];
    int lane  = threadIdx.x & 31;
    int wslot = threadIdx.x >> 5;
    int warpG = blockIdx.x * WPB + wslot;
    int nW    = gridDim.x * WPB;

    float rT[LBL];
    load_rowT(rT, lane);

    for (int node = warpG; node < level; node += nW) {
        float res = node_compute(child, em, node, lane,
                                 &s_e[wslot][0][0], &s_e[wslot][1][0], rT);
        out[node * LBL + lane] = res;
    }
}

// ---------------------------------------------------------------------------
// Tail: levels startLevel..1 fused in a single 1024-thread block.
// __syncthreads between levels gives the required ordering (global visibility
// within a block is guaranteed across __syncthreads).
// ---------------------------------------------------------------------------
__global__ void __launch_bounds__(1024)
tail_kernel(const float* __restrict__ emissions,
            const float* __restrict__ childIn,
            float* __restrict__ s0,
            float* __restrict__ s1,
            float* __restrict__ d_out,
            int startLevel)
{
    __shared__ __align__(16) float s_e[32][2][LBL];
    int lane  = threadIdx.x & 31;
    int wslot = threadIdx.x >> 5;

    float rT[LBL];
    load_rowT(rT, lane);

    const float* child = childIn;
    float* out = s0;
    for (int v = startLevel; v >= 1; v >>= 1) {
        const float* em = emissions + (size_t)(v - 1) * LBL;
        for (int node = wslot; node < v; node += 32) {
            float res = node_compute(child, em, node, lane,
                                     &s_e[wslot][0][0], &s_e[wslot][1][0], rT);
            if (v > 1) out[node * LBL + lane] = res;
            else       d_out[lane] = res;
        }
        __syncthreads();
        child = out;
        out   = (out == s0) ? s1 : s0;
    }
}

// ---------------------------------------------------------------------------
// Launch: exp(trans) once, then one kernel per level down to 128, then the
// fused tail (64..1). Ping-pong between two static device buffers.
// ---------------------------------------------------------------------------
extern "C" void kernel_launch(void* const* d_in, const int* in_sizes, int n_in,
                              void* d_out, int out_size)
{
    const float* emissions = (const float*)d_in[0];
    const float* trans     = (const float*)d_in[1];
    float* out = (float*)d_out;

    int n_nodes  = in_sizes[0] / LBL;
    int n_leaves = (n_nodes + 1) / 2;

    void *pA, *pB;
    cudaGetSymbolAddress(&pA, g_bufA);
    cudaGetSymbolAddress(&pB, g_bufB);
    float* A = (float*)pA;
    float* B = (float*)pB;

    expT_kernel<<<1, 1024>>>(trans);

    const float* child = emissions + (size_t)(n_leaves - 1) * LBL;  // leaves
    float* dst = A;
    int v = n_leaves / 2;
    for (; v >= 128; v >>= 1) {
        int grid = (v + WPB - 1) / WPB;
        if (grid > 1480) grid = 1480;
        level_kernel<<<grid, WPB * 32>>>(
            child, emissions + (size_t)(v - 1) * LBL, dst, v);
        child = dst;
        dst = (dst == A) ? B : A;
    }

    // v is now 64 (for n_leaves = 131072). dst != child by construction.
    float* other = (dst == A) ? B : A;   // == child's buffer, safe after read
    tail_kernel<<<1, 1024>>>(emissions, child, dst, other, out, v);
}

// round 4
// speedup vs baseline: 1.6883x; 1.6883x over previous
#include <cuda_runtime.h>

#define LBL 32
#define WPB 8   // warps per block

// Static device scratch (allocation-free per harness rules).
__device__ __align__(16) float g_bufA[16384 * LBL];
__device__ __align__(16) float g_bufB[2048 * LBL];

// Each thread loads exp(trans[lane, :]) into registers (row of expT).
__device__ __forceinline__ void load_expT(float rT[LBL],
                                          const float* __restrict__ trans,
                                          int lane) {
    #pragma unroll
    for (int j = 0; j < 8; j++) {
        float4 v = ((const float4*)trans)[lane * 8 + j];
        rT[4 * j + 0] = __expf(v.x);
        rT[4 * j + 1] = __expf(v.y);
        rT[4 * j + 2] = __expf(v.z);
        rT[4 * j + 3] = __expf(v.w);
    }
}

// ---------------------------------------------------------------------------
// Per-node compute with PER-CHILD stabilization (required: sibling scores can
// differ by hundreds at upper levels; a shared max underflows the weaker
// child's exponentials):
//   out[l] = em[l] + ml + mr + log( dot(expT[l,:],eL) * dot(expT[l,:],eR) )
// Each dot is in [e^-5, ~1600], so the fused log is safe.
// ---------------------------------------------------------------------------
__device__ __forceinline__ float node_compute(
    const float* __restrict__ crow,    // left child row; right is contiguous
    float emv, int lane,
    float* __restrict__ s_el,          // 32 floats, 16B aligned, per-warp
    float* __restrict__ s_er,
    const float rT[LBL])
{
    float lv = crow[lane];
    float rv = crow[LBL + lane];

    float ml = lv, mr = rv;
    #pragma unroll
    for (int o = 16; o; o >>= 1) {
        ml = fmaxf(ml, __shfl_xor_sync(0xffffffffu, ml, o));
        mr = fmaxf(mr, __shfl_xor_sync(0xffffffffu, mr, o));
    }

    s_el[lane] = __expf(lv - ml);
    s_er[lane] = __expf(rv - mr);
    __syncwarp();

    // dot(expT[lane,:], e{L,R}) — broadcast LDS.128 reads, 2 accumulators each
    const float4* pel = (const float4*)s_el;
    const float4* per = (const float4*)s_er;
    float aL0 = 0.f, aL1 = 0.f, aR0 = 0.f, aR1 = 0.f;
    #pragma unroll
    for (int j = 0; j < 8; j += 2) {
        float4 a0 = pel[j], b0 = per[j];
        float4 a1 = pel[j + 1], b1 = per[j + 1];
        aL0 = fmaf(rT[4 * j + 0], a0.x, aL0);
        aL0 = fmaf(rT[4 * j + 1], a0.y, aL0);
        aL0 = fmaf(rT[4 * j + 2], a0.z, aL0);
        aL0 = fmaf(rT[4 * j + 3], a0.w, aL0);
        aL1 = fmaf(rT[4 * j + 4], a1.x, aL1);
        aL1 = fmaf(rT[4 * j + 5], a1.y, aL1);
        aL1 = fmaf(rT[4 * j + 6], a1.z, aL1);
        aL1 = fmaf(rT[4 * j + 7], a1.w, aL1);
        aR0 = fmaf(rT[4 * j + 0], b0.x, aR0);
        aR0 = fmaf(rT[4 * j + 1], b0.y, aR0);
        aR0 = fmaf(rT[4 * j + 2], b0.z, aR0);
        aR0 = fmaf(rT[4 * j + 3], b0.w, aR0);
        aR1 = fmaf(rT[4 * j + 4], b1.x, aR1);
        aR1 = fmaf(rT[4 * j + 5], b1.y, aR1);
        aR1 = fmaf(rT[4 * j + 6], b1.z, aR1);
        aR1 = fmaf(rT[4 * j + 7], b1.w, aR1);
    }
    float res = emv + ml + mr + __logf((aL0 + aL1) * (aR0 + aR1));
    __syncwarp();   // protect shared staging before next iteration's writes
    return res;
}

// ---------------------------------------------------------------------------
// Fused 3-level kernel. Block b produces 8 output rows at level V/4 from
// 64 child rows (global); the two intermediate levels live in shared memory.
// Output slabs are disjoint across blocks.
// ---------------------------------------------------------------------------
__global__ void __launch_bounds__(WPB * 32)
fused3_kernel(const float* __restrict__ child,      // 2*V rows
              const float* __restrict__ emissions,
              const float* __restrict__ trans,
              float* __restrict__ out,              // V/4 rows
              int V)
{
    __shared__ __align__(16) float s1[32 * LBL];    // level-V slice
    __shared__ __align__(16) float s2[16 * LBL];    // level-V/2 slice
    __shared__ __align__(16) float stg[WPB][2 * LBL];

    int lane = threadIdx.x & 31;
    int w    = threadIdx.x >> 5;

    float rT[LBL];
    load_expT(rT, trans, lane);

    const float* em1 = emissions + (size_t)(V - 1) * LBL;
    const float* em2 = emissions + (size_t)(V / 2 - 1) * LBL;
    const float* em3 = emissions + (size_t)(V / 4 - 1) * LBL;

    // Stage 1: 32 nodes at level V, children from global.
    int base1 = blockIdx.x * 32;
    #pragma unroll
    for (int i = 0; i < 4; i++) {
        int n = i * WPB + w;               // 0..31 local
        int g = base1 + n;
        float r = node_compute(child + (size_t)(2 * g) * LBL,
                               em1[(size_t)g * LBL + lane], lane,
                               stg[w], stg[w] + LBL, rT);
        s1[n * LBL + lane] = r;
    }
    __syncthreads();

    // Stage 2: 16 nodes at level V/2, children in s1.
    int base2 = blockIdx.x * 16;
    #pragma unroll
    for (int i = 0; i < 2; i++) {
        int n = i * WPB + w;               // 0..15 local
        float r = node_compute(s1 + 2 * n * LBL,
                               em2[(size_t)(base2 + n) * LBL + lane], lane,
                               stg[w], stg[w] + LBL, rT);
        s2[n * LBL + lane] = r;
    }
    __syncthreads();

    // Stage 3: 8 nodes at level V/4, children in s2, write global.
    int base3 = blockIdx.x * 8;
    {
        int n = w;                         // 0..7 local
        float r = node_compute(s2 + 2 * n * LBL,
                               em3[(size_t)(base3 + n) * LBL + lane], lane,
                               stg[w], stg[w] + LBL, rT);
        out[(size_t)(base3 + n) * LBL + lane] = r;
    }
}

// ---------------------------------------------------------------------------
// Tail: levels startV..1 (startV <= 32) in one block, smem ping-pong.
// ---------------------------------------------------------------------------
__global__ void __launch_bounds__(WPB * 32)
tail_kernel(const float* __restrict__ child,        // 2*startV rows
            const float* __restrict__ emissions,
            const float* __restrict__ trans,
            float* __restrict__ d_out,
            int startV)
{
    __shared__ __align__(16) float sa[32 * LBL];
    __shared__ __align__(16) float sb[16 * LBL];
    __shared__ __align__(16) float stg[WPB][2 * LBL];

    int lane = threadIdx.x & 31;
    int w    = threadIdx.x >> 5;

    float rT[LBL];
    load_expT(rT, trans, lane);

    const float* c = child;
    float* o = sa;
    for (int v = startV; v >= 1; v >>= 1) {
        const float* em = emissions + (size_t)(v - 1) * LBL;
        for (int n = w; n < v; n += WPB) {
            float r = node_compute(c + (size_t)(2 * n) * LBL,
                                   em[n * LBL + lane], lane,
                                   stg[w], stg[w] + LBL, rT);
            if (v > 1) o[n * LBL + lane] = r;
            else       d_out[lane] = r;
        }
        __syncthreads();
        c = o;
        o = (o == sa) ? sb : sa;
    }
}

// ---------------------------------------------------------------------------
// Launch chain (n_leaves = 131072):
//   fused3 V=65536 -> A(16384 rows)
//   fused3 V=8192  -> B(2048)
//   fused3 V=1024  -> A(256)
//   fused3 V=128   -> B(32)
//   tail   startV=16 -> d_out
// 5 graph nodes total.
// ---------------------------------------------------------------------------
extern "C" void kernel_launch(void* const* d_in, const int* in_sizes, int n_in,
                              void* d_out, int out_size)
{
    const float* emissions = (const float*)d_in[0];
    const float* trans     = (const float*)d_in[1];
    float* out = (float*)d_out;

    int n_nodes  = in_sizes[0] / LBL;
    int n_leaves = (n_nodes + 1) / 2;

    void *pA, *pB;
    cudaGetSymbolAddress(&pA, g_bufA);
    cudaGetSymbolAddress(&pB, g_bufB);
    float* bufs[2] = { (float*)pA, (float*)pB };

    const float* child = emissions + (size_t)(n_leaves - 1) * LBL;  // leaves
    int V = n_leaves / 2;
    int t = 0;
    while (V >= 128) {
        float* dst = bufs[t & 1];
        t++;
        fused3_kernel<<<V / 32, WPB * 32>>>(child, emissions, trans, dst, V);
        child = dst;
        V >>= 3;
    }
    // V is now 16 for n_leaves = 131072 (child holds the level-32 scores).
    tail_kernel<<<1, WPB * 32>>>(child, emissions, trans, out, V);
}

// round 5
// speedup vs baseline: 2.2095x; 1.3087x over previous
#include <cuda_runtime.h>

#define LBL 32
#define WPB 8   // warps per block

// Static device scratch (allocation-free per harness rules).
// Distinct buffer per phase -> every inter-phase address is read once per
// launch (no cross-SM L1 staleness; L1 is flushed at launch boundaries).
__device__ __align__(16) float g_A[16384 * LBL];
__device__ __align__(16) float g_B[2048 * LBL];
__device__ __align__(16) float g_C[256 * LBL];
__device__ __align__(16) float g_D[32 * LBL];

// Grid barrier state (re-entrant across graph replays: count returns to 0,
// phase is monotone and sampled at kernel start).
__device__ unsigned g_bar_count = 0;
__device__ unsigned g_bar_phase = 0;

__device__ __forceinline__ void grid_barrier(unsigned nblocks, unsigned& myphase) {
    __syncthreads();
    if (threadIdx.x == 0) {
        __threadfence();
        unsigned arr = atomicAdd(&g_bar_count, 1u);
        if (arr == nblocks - 1u) {
            g_bar_count = 0;          // all arrived; safe to reset
            __threadfence();
            atomicAdd(&g_bar_phase, 1u);   // release
        } else {
            while (*(volatile unsigned*)&g_bar_phase == myphase)
                __nanosleep(64);
        }
    }
    __syncthreads();
    myphase++;
}

// Each thread loads exp(trans[lane, :]) into registers (row of expT).
__device__ __forceinline__ void load_expT(float rT[LBL],
                                          const float* __restrict__ trans,
                                          int lane) {
    #pragma unroll
    for (int j = 0; j < 8; j++) {
        float4 v = ((const float4*)trans)[lane * 8 + j];
        rT[4 * j + 0] = __expf(v.x);
        rT[4 * j + 1] = __expf(v.y);
        rT[4 * j + 2] = __expf(v.z);
        rT[4 * j + 3] = __expf(v.w);
    }
}

// ---------------------------------------------------------------------------
// Per-node compute with PER-CHILD stabilization (sibling scores can differ
// by hundreds at upper levels; a shared max underflows the weaker child):
//   out[l] = em[l] + ml + mr + log( dot(expT[l,:],eL) * dot(expT[l,:],eR) )
// Each dot is in (1, ~1600], so the fused log is safe.
// Inputs lv/rv/emv are preloaded by the caller (enables prefetch).
// ---------------------------------------------------------------------------
__device__ __forceinline__ float node_core(
    float lv, float rv, float emv, int lane,
    float* __restrict__ s_el, float* __restrict__ s_er,
    const float rT[LBL])
{
    float ml = lv, mr = rv;
    #pragma unroll
    for (int o = 16; o; o >>= 1) {
        ml = fmaxf(ml, __shfl_xor_sync(0xffffffffu, ml, o));
        mr = fmaxf(mr, __shfl_xor_sync(0xffffffffu, mr, o));
    }

    s_el[lane] = __expf(lv - ml);
    s_er[lane] = __expf(rv - mr);
    __syncwarp();

    const float4* pel = (const float4*)s_el;
    const float4* per = (const float4*)s_er;
    float aL0 = 0.f, aL1 = 0.f, aR0 = 0.f, aR1 = 0.f;
    #pragma unroll
    for (int j = 0; j < 8; j += 2) {
        float4 a0 = pel[j], b0 = per[j];
        float4 a1 = pel[j + 1], b1 = per[j + 1];
        aL0 = fmaf(rT[4 * j + 0], a0.x, aL0);
        aL0 = fmaf(rT[4 * j + 1], a0.y, aL0);
        aL0 = fmaf(rT[4 * j + 2], a0.z, aL0);
        aL0 = fmaf(rT[4 * j + 3], a0.w, aL0);
        aL1 = fmaf(rT[4 * j + 4], a1.x, aL1);
        aL1 = fmaf(rT[4 * j + 5], a1.y, aL1);
        aL1 = fmaf(rT[4 * j + 6], a1.z, aL1);
        aL1 = fmaf(rT[4 * j + 7], a1.w, aL1);
        aR0 = fmaf(rT[4 * j + 0], b0.x, aR0);
        aR0 = fmaf(rT[4 * j + 1], b0.y, aR0);
        aR0 = fmaf(rT[4 * j + 2], b0.z, aR0);
        aR0 = fmaf(rT[4 * j + 3], b0.w, aR0);
        aR1 = fmaf(rT[4 * j + 4], b1.x, aR1);
        aR1 = fmaf(rT[4 * j + 5], b1.y, aR1);
        aR1 = fmaf(rT[4 * j + 6], b1.z, aR1);
        aR1 = fmaf(rT[4 * j + 7], b1.w, aR1);
    }
    float res = emv + ml + mr + __logf((aL0 + aL1) * (aR0 + aR1));
    __syncwarp();   // protect shared staging before next call's writes
    return res;
}

// ---------------------------------------------------------------------------
// Persistent kernel: all levels in one launch, grid barrier between fused-3
// groups. Each slab s covers 32 nodes at level V -> 16 -> 8 (disjoint across
// slabs; intermediate levels in shared memory).
// ---------------------------------------------------------------------------
__global__ void __launch_bounds__(WPB * 32, 3)
persistent_kernel(const float* __restrict__ emissions,
                  const float* __restrict__ trans,
                  float* __restrict__ d_out,
                  int n_leaves)
{
    __shared__ __align__(16) float s1[32 * LBL];
    __shared__ __align__(16) float s2[16 * LBL];
    __shared__ __align__(16) float stg[WPB][2 * LBL];

    int lane = threadIdx.x & 31;
    int w    = threadIdx.x >> 5;
    unsigned nblocks = gridDim.x;

    // Sample barrier phase before any barrier can release (all blocks are
    // resident and must arrive before release, so this read is race-free).
    unsigned myphase = *(volatile unsigned*)&g_bar_phase;

    float rT[LBL];
    load_expT(rT, trans, lane);

    float* bufs[4] = { g_A, g_B, g_C, g_D };
    const float* child = emissions + (size_t)(n_leaves - 1) * LBL;  // leaves

    int V = n_leaves / 2;
    int bi = 0;
    while (V >= 128) {
        float* out = bufs[bi++];
        const float* em1 = emissions + (size_t)(V - 1) * LBL;
        const float* em2 = emissions + (size_t)(V / 2 - 1) * LBL;
        const float* em3 = emissions + (size_t)(V / 4 - 1) * LBL;
        int nslabs = V / 32;

        for (int s = blockIdx.x; s < nslabs; s += nblocks) {
            // ---- Stage 1: 32 nodes at level V, children from global,
            //      depth-1 prefetch of the next node's loads.
            int g0 = s * 32 + w;             // i = 0
            float lv = child[(size_t)(2 * g0) * LBL + lane];
            float rv = child[(size_t)(2 * g0) * LBL + LBL + lane];
            float ev = em1[(size_t)g0 * LBL + lane];
            #pragma unroll
            for (int i = 0; i < 4; i++) {
                float lv2, rv2, ev2;
                if (i < 3) {
                    int g = s * 32 + (i + 1) * WPB + w;
                    lv2 = child[(size_t)(2 * g) * LBL + lane];
                    rv2 = child[(size_t)(2 * g) * LBL + LBL + lane];
                    ev2 = em1[(size_t)g * LBL + lane];
                }
                float r = node_core(lv, rv, ev, lane, stg[w], stg[w] + LBL, rT);
                s1[(i * WPB + w) * LBL + lane] = r;
                lv = lv2; rv = rv2; ev = ev2;
            }
            __syncthreads();

            // ---- Stage 2: 16 nodes at level V/2, children in s1.
            #pragma unroll
            for (int i = 0; i < 2; i++) {
                int n = i * WPB + w;
                float lvs = s1[2 * n * LBL + lane];
                float rvs = s1[2 * n * LBL + LBL + lane];
                float evs = em2[(size_t)(s * 16 + n) * LBL + lane];
                float r = node_core(lvs, rvs, evs, lane, stg[w], stg[w] + LBL, rT);
                s2[n * LBL + lane] = r;
            }
            __syncthreads();

            // ---- Stage 3: 8 nodes at level V/4, children in s2 -> global.
            {
                int n = w;
                float lvs = s2[2 * n * LBL + lane];
                float rvs = s2[2 * n * LBL + LBL + lane];
                float evs = em3[(size_t)(s * 8 + n) * LBL + lane];
                float r = node_core(lvs, rvs, evs, lane, stg[w], stg[w] + LBL, rT);
                out[(size_t)(s * 8 + n) * LBL + lane] = r;
            }
            __syncthreads();   // s1/s2 reuse safety for next slab
        }

        grid_barrier(nblocks, myphase);
        child = out;
        V >>= 3;
    }

    // ---- Tail: remaining levels (V=16..1 for n_leaves=131072), block 0 only.
    if (blockIdx.x == 0) {
        const float* c = child;
        float* o = s1;
        for (int v = V; v >= 1; v >>= 1) {
            const float* em = emissions + (size_t)(v - 1) * LBL;
            for (int n = w; n < v; n += WPB) {
                float lvs = c[(size_t)(2 * n) * LBL + lane];
                float rvs = c[(size_t)(2 * n) * LBL + LBL + lane];
                float evs = em[(size_t)n * LBL + lane];
                float r = node_core(lvs, rvs, evs, lane, stg[w], stg[w] + LBL, rT);
                if (v > 1) o[n * LBL + lane] = r;
                else       d_out[lane] = r;
            }
            __syncthreads();
            c = o;
            o = (o == s1) ? s2 : s1;   // v<=16 fits in s2 (16 rows)
        }
    }
}

// ---------------------------------------------------------------------------
// One graph node. Grid sized so ALL blocks are simultaneously resident
// (required by the software grid barrier).
// ---------------------------------------------------------------------------
extern "C" void kernel_launch(void* const* d_in, const int* in_sizes, int n_in,
                              void* d_out, int out_size)
{
    const float* emissions = (const float*)d_in[0];
    const float* trans     = (const float*)d_in[1];
    float* out = (float*)d_out;

    int n_nodes  = in_sizes[0] / LBL;
    int n_leaves = (n_nodes + 1) / 2;

    static int grid = 0;
    if (grid == 0) {
        int dev = 0, sms = 0, perSM = 0;
        cudaGetDevice(&dev);
        cudaDeviceGetAttribute(&sms, cudaDevAttrMultiProcessorCount, dev);
        cudaOccupancyMaxActiveBlocksPerMultiprocessor(
            &perSM, persistent_kernel, WPB * 32, 0);
        if (perSM < 1) perSM = 1;
        grid = sms * perSM;
        int maxSlabs = (n_leaves / 2) / 32;
        if (grid > maxSlabs) grid = maxSlabs;
        if (grid < 1) grid = 1;
    }

    persistent_kernel<<<grid, WPB * 32>>>(emissions, trans, out, n_leaves);
}